// round 1
// baseline (speedup 1.0000x reference)
#include <cuda_runtime.h>

typedef unsigned long long ULL;

// ---- packed f32x2 helpers (Blackwell sm_103a) ----
__device__ __forceinline__ ULL pack2(float lo, float hi) {
    ULL r;
    asm("mov.b64 %0, {%1, %2};" : "=l"(r) : "f"(lo), "f"(hi));
    return r;
}
__device__ __forceinline__ void fma2(ULL& d, ULL a, ULL b) {
    asm("fma.rn.f32x2 %0, %1, %2, %0;" : "+l"(d) : "l"(a), "l"(b));
}
__device__ __forceinline__ float2 unpack2(ULL v) {
    float2 r;
    asm("mov.b64 {%0, %1}, %2;" : "=f"(r.x), "=f"(r.y) : "l"(v));
    return r;
}

// ---- problem constants ----
constexpr int N   = 49;    // tokens per window (7x7x1)
constexpr int D   = 128;   // model dim
constexpr int H   = 4;     // heads
constexpr int DH  = 32;    // head dim
constexpr int D3  = 384;   // 3*D
constexpr int XS  = 52;    // padded i-stride for transposed tiles (mult of 4, covers pair tail)
constexpr float SCALE = 0.17677669529663687f;  // 32^-0.5

// smem layout (floats)
constexpr int OFF_XT   = 0;                    // [D][XS]  (also reused as transposed attn output)
constexpr int OFF_QS   = OFF_XT + D * XS;      // [H][N][DH]
constexpr int OFF_KS   = OFF_QS + H * N * DH;
constexpr int OFF_VS   = OFF_KS + H * N * DH;
constexpr int OFF_BS   = OFF_VS + H * N * DH;  // [169][H]
constexpr int OFF_AT   = OFF_BS + 169 * H;     // [196][49] attention rows
constexpr int SMEM_FLOATS = OFF_AT + H * N * N;
constexpr size_t SMEM_BYTES = (size_t)SMEM_FLOATS * sizeof(float);

__global__ __launch_bounds__(384, 1)
void win_attn_kernel(const float* __restrict__ x,
                     const float* __restrict__ wqkv,
                     const float* __restrict__ wout,
                     const float* __restrict__ btab,
                     float* __restrict__ out)
{
    extern __shared__ float sm[];
    float* xt = sm + OFF_XT;
    float* qs = sm + OFF_QS;
    float* ks = sm + OFF_KS;
    float* vs = sm + OFF_VS;
    float* bs = sm + OFF_BS;
    float* at = sm + OFF_AT;

    const int t = threadIdx.x;
    const size_t win = blockIdx.x;
    const float* xw = x + win * (size_t)(N * D);
    float* ow = out + win * (size_t)(N * D);

    // zero the transposed x tile (pads included -> no NaN in the pair tail)
    for (int idx = t; idx < D * XS; idx += 384) xt[idx] = 0.0f;
    // stage bias table
    for (int idx = t; idx < 169 * H; idx += 384) bs[idx] = btab[idx];
    __syncthreads();

    // load x (49x128, row-major) -> xt[k][i] transposed; coalesced over k
    for (int idx = t; idx < N * D; idx += 384) {
        int i = idx >> 7;       // idx / 128
        int k = idx & 127;
        xt[k * XS + i] = xw[idx];
    }
    __syncthreads();

    // ================= Phase 1: QKV GEMM (49x128 @ 128x384) =================
    // thread t owns output column j = t. 25 packed accumulators cover i=0..49.
    {
        ULL acc[25];
#pragma unroll
        for (int p = 0; p < 25; p++) acc[p] = 0ull;

        const float* wc = wqkv + t;
#pragma unroll 4
        for (int k = 0; k < D; k++) {
            float wk = __ldg(wc + k * D3);
            ULL w2 = pack2(wk, wk);
            const ulonglong2* xr = reinterpret_cast<const ulonglong2*>(xt + k * XS);
#pragma unroll
            for (int p = 0; p < 12; p++) {          // i = 0..47
                ulonglong2 a = xr[p];
                fma2(acc[2 * p],     a.x, w2);
                fma2(acc[2 * p + 1], a.y, w2);
            }
            ULL tail = reinterpret_cast<const ULL*>(xt + k * XS)[24];  // i = 48,49(pad=0)
            fma2(acc[24], tail, w2);
        }

        const int sel = t >> 7;           // 0=q, 1=k, 2=v
        const int jj  = t & 127;
        const int h   = jj >> 5;
        const int dd  = jj & 31;
        float* dst = (sel == 0 ? qs : (sel == 1 ? ks : vs)) + (h * N) * DH + dd;
        const float scl = (sel == 0) ? SCALE : 1.0f;
#pragma unroll
        for (int p = 0; p < 25; p++) {
            float2 f = unpack2(acc[p]);
            int i0 = 2 * p;
            dst[i0 * DH] = f.x * scl;
            if (i0 + 1 < N) dst[(i0 + 1) * DH] = f.y * scl;
        }
    }
    __syncthreads();

    // ================= Phase 2: attention (per (head,row) thread) ============
    if (t < H * N) {
        const int h = t / N;
        const int i = t - h * N;

        // q row -> 16 packed regs
        ULL q2[16];
        const ulonglong2* qr = reinterpret_cast<const ulonglong2*>(qs + (h * N + i) * DH);
#pragma unroll
        for (int p = 0; p < 8; p++) {
            ulonglong2 a = qr[p];
            q2[2 * p]     = a.x;
            q2[2 * p + 1] = a.y;
        }

        const int gi1 = i / 7;
        const int gj1 = i - 7 * gi1;
        float* arow = at + t * N;
        float mx = -1e30f;

        for (int jj = 0; jj < N; jj++) {
            const ulonglong2* kr = reinterpret_cast<const ulonglong2*>(ks + (h * N + jj) * DH);
            ULL d0 = 0ull, d1 = 0ull;
#pragma unroll
            for (int p = 0; p < 8; p++) {
                ulonglong2 a = kr[p];
                fma2(d0, q2[2 * p],     a.x);
                fma2(d1, q2[2 * p + 1], a.y);
            }
            float2 s0 = unpack2(d0), s1 = unpack2(d1);
            float s = (s0.x + s0.y) + (s1.x + s1.y);

            int gi2 = jj / 7;
            int gj2 = jj - 7 * gi2;
            int bidx = (gi1 - gi2 + 6) * 13 + (gj1 - gj2 + 6);
            s += bs[bidx * H + h];

            arow[jj] = s;
            mx = fmaxf(mx, s);
        }

        float sum = 0.0f;
        for (int jj = 0; jj < N; jj++) {
            float e = __expf(arow[jj] - mx);
            arow[jj] = e;
            sum += e;
        }
        const float inv = 1.0f / sum;

        // out row = attn @ V  (32 dims, 16 packed accumulators)
        ULL o2[16];
#pragma unroll
        for (int p = 0; p < 16; p++) o2[p] = 0ull;
        for (int jj = 0; jj < N; jj++) {
            float a = arow[jj];
            ULL a2 = pack2(a, a);
            const ulonglong2* vr = reinterpret_cast<const ulonglong2*>(vs + (h * N + jj) * DH);
#pragma unroll
            for (int p = 0; p < 8; p++) {
                ulonglong2 b = vr[p];
                fma2(o2[2 * p],     a2, b.x);
                fma2(o2[2 * p + 1], a2, b.y);
            }
        }

        // write transposed attention output into the (now dead) xt region:
        // ot[k2][i], k2 = h*32+dd
        float* ot = xt;
#pragma unroll
        for (int p = 0; p < 16; p++) {
            float2 f = unpack2(o2[p]);
            int dd = 2 * p;
            ot[(h * DH + dd) * XS + i]     = f.x * inv;
            ot[(h * DH + dd + 1) * XS + i] = f.y * inv;
        }
    }
    __syncthreads();

    // ================= Phase 3: out-proj (49x128 @ 128x128) ==================
    // 3 groups x 128 columns; group g owns 16 rows (group 2 owns 17: +row 48)
    {
        const int g  = t >> 7;          // 0..2
        const int j  = t & 127;
        const int i0 = g * 16;
        const float* ot = xt;

        ULL acc[8];
#pragma unroll
        for (int p = 0; p < 8; p++) acc[p] = 0ull;
        float acc48 = 0.0f;

        const float* wc = wout + j;
#pragma unroll 2
        for (int k = 0; k < D; k++) {
            float wk = __ldg(wc + k * D);
            ULL w2 = pack2(wk, wk);
            const ulonglong2* orow = reinterpret_cast<const ulonglong2*>(ot + k * XS + i0);
#pragma unroll
            for (int p = 0; p < 4; p++) {
                ulonglong2 a = orow[p];
                fma2(acc[2 * p],     a.x, w2);
                fma2(acc[2 * p + 1], a.y, w2);
            }
            if (g == 2) acc48 = fmaf(ot[k * XS + 48], wk, acc48);
        }

#pragma unroll
        for (int p = 0; p < 8; p++) {
            float2 f = unpack2(acc[p]);
            ow[(i0 + 2 * p) * D + j]     = f.x;
            ow[(i0 + 2 * p + 1) * D + j] = f.y;
        }
        if (g == 2) ow[48 * D + j] = acc48;
    }
}

extern "C" void kernel_launch(void* const* d_in, const int* in_sizes, int n_in,
                              void* d_out, int out_size) {
    const float* x    = (const float*)d_in[0];
    const float* wqkv = (const float*)d_in[1];
    const float* wout = (const float*)d_in[2];
    const float* btab = (const float*)d_in[3];
    float* out = (float*)d_out;

    const int n_win = in_sizes[0] / (N * D);   // 8192 windows

    cudaFuncSetAttribute(win_attn_kernel,
                         cudaFuncAttributeMaxDynamicSharedMemorySize,
                         (int)SMEM_BYTES);
    win_attn_kernel<<<n_win, 384, SMEM_BYTES>>>(x, wqkv, wout, btab, out);
}

// round 2
// speedup vs baseline: 1.0233x; 1.0233x over previous
#include <cuda_runtime.h>

typedef unsigned long long ULL;

// ---- packed f32x2 helpers (Blackwell sm_103a) ----
__device__ __forceinline__ ULL pack2(float lo, float hi) {
    ULL r;
    asm("mov.b64 %0, {%1, %2};" : "=l"(r) : "f"(lo), "f"(hi));
    return r;
}
__device__ __forceinline__ void fma2(ULL& d, ULL a, ULL b) {
    asm("fma.rn.f32x2 %0, %1, %2, %0;" : "+l"(d) : "l"(a), "l"(b));
}
__device__ __forceinline__ float2 unpack2(ULL v) {
    float2 r;
    asm("mov.b64 {%0, %1}, %2;" : "=f"(r.x), "=f"(r.y) : "l"(v));
    return r;
}

// ---- problem constants ----
constexpr int N   = 49;    // tokens per window (7x7x1)
constexpr int D   = 128;   // model dim
constexpr int H   = 4;     // heads
constexpr int DH  = 32;    // head dim
constexpr int D3  = 384;   // 3*D
constexpr int XS  = 52;    // padded i-stride for transposed tiles
constexpr float SCALE = 0.17677669529663687f;  // 32^-0.5

// smem layout (floats)
constexpr int OFF_XT = 0;                    // [128][52]; reused as transposed attn-out in ph2/3
constexpr int OFF_QS = OFF_XT + D * XS;      // [H][N][DH]
constexpr int OFF_KS = OFF_QS + H * N * DH;
constexpr int OFF_VS = OFF_KS + H * N * DH;
constexpr int OFF_BS = OFF_VS + H * N * DH;  // [169][H]
constexpr int SMEM_FLOATS = OFF_BS + 169 * H;
constexpr size_t SMEM_BYTES = (size_t)SMEM_FLOATS * sizeof(float);

__global__ __launch_bounds__(384, 1)
void win_attn_kernel(const float* __restrict__ x,
                     const float* __restrict__ wqkv,
                     const float* __restrict__ wout,
                     const float* __restrict__ btab,
                     float* __restrict__ out)
{
    extern __shared__ float sm[];
    float* xt = sm + OFF_XT;
    float* qs = sm + OFF_QS;
    float* ks = sm + OFF_KS;
    float* vs = sm + OFF_VS;
    float* bs = sm + OFF_BS;

    const int t = threadIdx.x;
    const size_t win = blockIdx.x;
    const float* xw = x + win * (size_t)(N * D);
    float* ow = out + win * (size_t)(N * D);

    // stage bias table
    for (int idx = t; idx < 169 * H; idx += 384) bs[idx] = btab[idx];

    // load x (49x128 row-major) -> xt[k][i] transposed; coalesced over k
    for (int idx = t; idx < N * D; idx += 384) {
        int i = idx >> 7;
        int k = idx & 127;
        xt[k * XS + i] = xw[idx];
    }
    __syncthreads();

    // ================= Phase 1: QKV GEMM (49x128 @ 128x384) =================
    // 96 col-threads x 4 cols; 4 row-groups {16,16,16,1}. Warp = const tr.
    {
        const int tr = t / 96;          // row group
        const int tc = t % 96;          // col group
        const int j0 = tc * 4;
        const int sel = j0 >> 7;        // 0=q,1=k,2=v
        const int hh  = (j0 & 127) >> 5;
        const int dd  = j0 & 31;
        float* dst = (sel == 0 ? qs : (sel == 1 ? ks : vs)) + (hh * N) * DH + dd;
        const float scl = (sel == 0) ? SCALE : 1.0f;
        const float4* wp = reinterpret_cast<const float4*>(wqkv + j0);

        if (tr < 3) {
            const int i0 = tr * 16;
            ULL acc[32];
#pragma unroll
            for (int p = 0; p < 32; p++) acc[p] = 0ull;

            float4 w = __ldg(wp);
#pragma unroll 2
            for (int k = 0; k < D; k++) {
                float4 wn;
                if (k < D - 1) wn = __ldg(wp + (k + 1) * (D3 / 4));
                ULL wpk[4] = { pack2(w.x, w.x), pack2(w.y, w.y),
                               pack2(w.z, w.z), pack2(w.w, w.w) };
                const ulonglong2* xr =
                    reinterpret_cast<const ulonglong2*>(xt + k * XS + i0);
                ulonglong2 a0 = xr[0], a1 = xr[1], a2 = xr[2], a3 = xr[3];
                ULL av[8] = { a0.x, a0.y, a1.x, a1.y, a2.x, a2.y, a3.x, a3.y };
#pragma unroll
                for (int c = 0; c < 4; c++)
#pragma unroll
                    for (int r = 0; r < 8; r++)
                        fma2(acc[c * 8 + r], av[r], wpk[c]);
                w = wn;
            }
            // write 16 rows x 4 cols
#pragma unroll
            for (int r = 0; r < 8; r++) {
                float2 f0 = unpack2(acc[0 * 8 + r]);
                float2 f1 = unpack2(acc[1 * 8 + r]);
                float2 f2 = unpack2(acc[2 * 8 + r]);
                float2 f3 = unpack2(acc[3 * 8 + r]);
                int i = i0 + 2 * r;
                *reinterpret_cast<float4*>(dst + i * DH) =
                    make_float4(f0.x * scl, f1.x * scl, f2.x * scl, f3.x * scl);
                *reinterpret_cast<float4*>(dst + (i + 1) * DH) =
                    make_float4(f0.y * scl, f1.y * scl, f2.y * scl, f3.y * scl);
            }
        } else {
            // row 48 only
            float a4[4] = {0.f, 0.f, 0.f, 0.f};
            for (int k = 0; k < D; k++) {
                float xv = xt[k * XS + 48];
                float4 w = __ldg(wp + k * (D3 / 4));
                a4[0] = fmaf(xv, w.x, a4[0]);
                a4[1] = fmaf(xv, w.y, a4[1]);
                a4[2] = fmaf(xv, w.z, a4[2]);
                a4[3] = fmaf(xv, w.w, a4[3]);
            }
            *reinterpret_cast<float4*>(dst + 48 * DH) =
                make_float4(a4[0] * scl, a4[1] * scl, a4[2] * scl, a4[3] * scl);
        }
    }
    __syncthreads();

    // ================= Phase 2: attention, fused 2-pass softmax ==============
    if (t < H * N) {
        const int h = t / N;
        const int i = t - h * N;

        ULL q2[16];
        const ulonglong2* qr =
            reinterpret_cast<const ulonglong2*>(qs + (h * N + i) * DH);
#pragma unroll
        for (int p = 0; p < 8; p++) {
            ulonglong2 a = qr[p];
            q2[2 * p] = a.x;
            q2[2 * p + 1] = a.y;
        }

        const int gi1 = i / 7;
        const int gj1 = i - 7 * gi1;
        const float* bsp = bs + ((gi1 + 6) * 13 + (gj1 + 6)) * H + h;
        const float* krow = ks + h * N * DH;
        const float* vrow = vs + h * N * DH;

        // pass 1: row max
        float mx = -1e30f;
        {
            int l = 0, gj2 = 0;
            for (int j = 0; j < N; j++) {
                const ulonglong2* kr =
                    reinterpret_cast<const ulonglong2*>(krow + j * DH);
                ULL d0 = 0ull, d1 = 0ull;
#pragma unroll
                for (int p = 0; p < 8; p++) {
                    ulonglong2 a = kr[p];
                    fma2(d0, q2[2 * p], a.x);
                    fma2(d1, q2[2 * p + 1], a.y);
                }
                float2 s0 = unpack2(d0), s1 = unpack2(d1);
                float s = (s0.x + s0.y) + (s1.x + s1.y) + bsp[-l * H];
                mx = fmaxf(mx, s);
                if (++gj2 == 7) { gj2 = 0; l += 7; } else { l += 1; }
            }
        }

        // pass 2: recompute scores, exp, accumulate sum and unnormalized O
        ULL o2[16];
#pragma unroll
        for (int p = 0; p < 16; p++) o2[p] = 0ull;
        float sum = 0.0f;
        {
            int l = 0, gj2 = 0;
            for (int j = 0; j < N; j++) {
                const ulonglong2* kr =
                    reinterpret_cast<const ulonglong2*>(krow + j * DH);
                ULL d0 = 0ull, d1 = 0ull;
#pragma unroll
                for (int p = 0; p < 8; p++) {
                    ulonglong2 a = kr[p];
                    fma2(d0, q2[2 * p], a.x);
                    fma2(d1, q2[2 * p + 1], a.y);
                }
                float2 s0 = unpack2(d0), s1 = unpack2(d1);
                float s = (s0.x + s0.y) + (s1.x + s1.y) + bsp[-l * H];
                float e = __expf(s - mx);
                sum += e;
                ULL e2 = pack2(e, e);
                const ulonglong2* vr =
                    reinterpret_cast<const ulonglong2*>(vrow + j * DH);
#pragma unroll
                for (int p = 0; p < 8; p++) {
                    ulonglong2 b = vr[p];
                    fma2(o2[2 * p], e2, b.x);
                    fma2(o2[2 * p + 1], e2, b.y);
                }
                if (++gj2 == 7) { gj2 = 0; l += 7; } else { l += 1; }
            }
        }
        const float inv = 1.0f / sum;

        // write transposed attn-out into xt region: ot[h*32+dd][i]
        float* ot = xt;
#pragma unroll
        for (int p = 0; p < 16; p++) {
            float2 f = unpack2(o2[p]);
            ot[(h * DH + 2 * p) * XS + i]     = f.x * inv;
            ot[(h * DH + 2 * p + 1) * XS + i] = f.y * inv;
        }
    }
    __syncthreads();

    // ================= Phase 3: out-proj (49x128 @ 128x128) ==================
    // 32 col-threads x 4 cols; 12 row-groups of 4 rows (group 11 also row 48).
    {
        const int tr = t >> 5;          // 0..11 (warp = const tr)
        const int tc = t & 31;
        const int j0 = tc * 4;
        const int i0 = tr * 4;
        const float* ot = xt;
        const float4* wp = reinterpret_cast<const float4*>(wout + j0);

        ULL acc[8];
#pragma unroll
        for (int p = 0; p < 8; p++) acc[p] = 0ull;
        float a48[4] = {0.f, 0.f, 0.f, 0.f};

        float4 w = __ldg(wp);
#pragma unroll 2
        for (int k = 0; k < D; k++) {
            float4 wn;
            if (k < D - 1) wn = __ldg(wp + (k + 1) * (D / 4));
            ULL wpk[4] = { pack2(w.x, w.x), pack2(w.y, w.y),
                           pack2(w.z, w.z), pack2(w.w, w.w) };
            ulonglong2 a =
                *reinterpret_cast<const ulonglong2*>(ot + k * XS + i0);
#pragma unroll
            for (int c = 0; c < 4; c++) {
                fma2(acc[c * 2 + 0], a.x, wpk[c]);
                fma2(acc[c * 2 + 1], a.y, wpk[c]);
            }
            if (tr == 11) {
                float xv = ot[k * XS + 48];
                a48[0] = fmaf(xv, w.x, a48[0]);
                a48[1] = fmaf(xv, w.y, a48[1]);
                a48[2] = fmaf(xv, w.z, a48[2]);
                a48[3] = fmaf(xv, w.w, a48[3]);
            }
            w = wn;
        }

#pragma unroll
        for (int rp = 0; rp < 2; rp++) {
            float2 f0 = unpack2(acc[0 * 2 + rp]);
            float2 f1 = unpack2(acc[1 * 2 + rp]);
            float2 f2 = unpack2(acc[2 * 2 + rp]);
            float2 f3 = unpack2(acc[3 * 2 + rp]);
            int i = i0 + 2 * rp;
            *reinterpret_cast<float4*>(ow + i * D + j0) =
                make_float4(f0.x, f1.x, f2.x, f3.x);
            *reinterpret_cast<float4*>(ow + (i + 1) * D + j0) =
                make_float4(f0.y, f1.y, f2.y, f3.y);
        }
        if (tr == 11) {
            *reinterpret_cast<float4*>(ow + 48 * D + j0) =
                make_float4(a48[0], a48[1], a48[2], a48[3]);
        }
    }
}

extern "C" void kernel_launch(void* const* d_in, const int* in_sizes, int n_in,
                              void* d_out, int out_size) {
    const float* x    = (const float*)d_in[0];
    const float* wqkv = (const float*)d_in[1];
    const float* wout = (const float*)d_in[2];
    const float* btab = (const float*)d_in[3];
    float* out = (float*)d_out;

    const int n_win = in_sizes[0] / (N * D);   // 8192 windows

    cudaFuncSetAttribute(win_attn_kernel,
                         cudaFuncAttributeMaxDynamicSharedMemorySize,
                         (int)SMEM_BYTES);
    win_attn_kernel<<<n_win, 384, SMEM_BYTES>>>(x, wqkv, wout, btab, out);
}